// round 1
// baseline (speedup 1.0000x reference)
#include <cuda_runtime.h>
#include <cstdint>

// Problem constants
#define Bq     256
#define Tq     16
#define Cq     40
#define Hq     4
#define Dq     10
#define Vq     50257
#define BT     (Bq*Tq)          // 4096 rows
#define VPAD   50688            // 99*512, multiple of 4 (16B-aligned float4 rows)
#define NTILES 99               // ceil(V/512)
#define CPC    512              // columns per CTA
#define RPC    16               // rows per CTA
#define ROWTILES (BT/RPC)       // 256

// ---------------- device scratch (no allocations allowed) ----------------
__device__ float g_out[BT * Cq];            // attention output [row][C]
__device__ float g_Wpad[Cq * VPAD];         // padded lm_W, zero-filled tail
__device__ float g_pmax[BT * NTILES];       // per-(row,tile) chunk max
__device__ float g_psum[BT * NTILES];       // per-(row,tile) sum exp(v - chunkmax)
__device__ float g_tgt[BT];                 // logit at target column per row
__device__ float g_part[32];                // partial loss sums

// packed f32x2 helpers (Blackwell sm_103a)
__device__ __forceinline__ void fma2(unsigned long long& d, unsigned long long a,
                                     unsigned long long b, unsigned long long c) {
    asm("fma.rn.f32x2 %0, %1, %2, %3;" : "=l"(d) : "l"(a), "l"(b), "l"(c));
}
__device__ __forceinline__ unsigned long long pack2(float lo, float hi) {
    unsigned long long p;
    asm("mov.b64 %0, {%1, %2};" : "=l"(p) : "f"(lo), "f"(hi));
    return p;
}
__device__ __forceinline__ void unpack2(unsigned long long p, float& lo, float& hi) {
    asm("mov.b64 {%0, %1}, %2;" : "=f"(lo), "=f"(hi) : "l"(p));
}

// ---------------- kernel 0: pad lm_W [40,V] -> g_Wpad [40,VPAD] ----------------
__global__ void pad_kernel(const float* __restrict__ lm_W) {
    int i = blockIdx.x * blockDim.x + threadIdx.x;   // float4 index
    int n4 = Cq * VPAD / 4;
    if (i >= n4) return;
    int rowlen4 = VPAD / 4;
    int k = i / rowlen4;
    int c = (i - k * rowlen4) * 4;
    float4 w;
    w.x = (c + 0 < Vq) ? lm_W[k * Vq + c + 0] : 0.f;
    w.y = (c + 1 < Vq) ? lm_W[k * Vq + c + 1] : 0.f;
    w.z = (c + 2 < Vq) ? lm_W[k * Vq + c + 2] : 0.f;
    w.w = (c + 3 < Vq) ? lm_W[k * Vq + c + 3] : 0.f;
    *reinterpret_cast<float4*>(&g_Wpad[(size_t)k * VPAD + c]) = w;
}

// ---------------- kernel 1: embed + attention, one CTA per batch ----------------
__global__ __launch_bounds__(128)
void attn_kernel(const int* __restrict__ idx,
                 const float* __restrict__ tok_emb,
                 const float* __restrict__ pos_emb,
                 const float* __restrict__ Wq,
                 const float* __restrict__ Wk,
                 const float* __restrict__ Wv) {
    __shared__ float xs[Tq][Cq];
    __shared__ float qs[Hq][Tq][Dq];
    __shared__ float ks[Hq][Tq][Dq];
    __shared__ float vs[Hq][Tq][Dq];
    __shared__ float at[Hq][Tq][Tq];

    int b   = blockIdx.x;
    int tid = threadIdx.x;

    // x = tok_emb[idx] + pos_emb[t]
    for (int i = tid; i < Tq * Cq; i += 128) {
        int t = i / Cq, c = i - t * Cq;
        int tok = idx[b * Tq + t];
        xs[t][c] = tok_emb[(size_t)tok * Cq + c] + pos_emb[t * Cq + c];
    }
    __syncthreads();

    int h = tid >> 5, lane = tid & 31;   // one warp per head

    // q,k,v projections
    for (int i = lane; i < Tq * Dq; i += 32) {
        int t = i / Dq, d = i - t * Dq;
        float aq = 0.f, ak = 0.f, av = 0.f;
        #pragma unroll
        for (int c = 0; c < Cq; c++) {
            float x = xs[t][c];
            aq = fmaf(x, Wq[(h * Cq + c) * Dq + d], aq);
            ak = fmaf(x, Wk[(h * Cq + c) * Dq + d], ak);
            av = fmaf(x, Wv[(h * Cq + c) * Dq + d], av);
        }
        qs[h][t][d] = aq; ks[h][t][d] = ak; vs[h][t][d] = av;
    }
    __syncwarp();

    // att = q k^T (no 1/sqrt(d) scaling — faithful to reference), causal
    for (int i = lane; i < Tq * Tq; i += 32) {
        int t = i / Tq, s = i - t * Tq;
        float a;
        if (s <= t) {
            a = 0.f;
            #pragma unroll
            for (int d = 0; d < Dq; d++) a = fmaf(qs[h][t][d], ks[h][s][d], a);
        } else {
            a = -INFINITY;
        }
        at[h][t][s] = a;
    }
    __syncwarp();

    // softmax over each row (lanes 0..15 each own a row)
    if (lane < Tq) {
        int t = lane;
        float m = -INFINITY;
        for (int s = 0; s <= t; s++) m = fmaxf(m, at[h][t][s]);
        float sum = 0.f;
        for (int s = 0; s <= t; s++) { float e = expf(at[h][t][s] - m); at[h][t][s] = e; sum += e; }
        float inv = 1.f / sum;
        for (int s = 0; s <= t; s++) at[h][t][s] *= inv;
        for (int s = t + 1; s < Tq; s++) at[h][t][s] = 0.f;
    }
    __syncwarp();

    // out[t][h*D+d] = sum_s att * v
    for (int i = lane; i < Tq * Dq; i += 32) {
        int t = i / Dq, d = i - t * Dq;
        float a = 0.f;
        for (int s = 0; s <= t; s++) a = fmaf(at[h][t][s], vs[h][s][d], a);
        g_out[((size_t)(b * Tq + t)) * Cq + h * Dq + d] = a;
    }
}

// ---------------- kernel 2: logits GEMM + per-tile softmax partials ----------------
__global__ __launch_bounds__(128)
void logits_kernel(const float* __restrict__ lm_b,
                   const int* __restrict__ targets,
                   float* __restrict__ logits,
                   int write_logits) {
    __shared__ unsigned long long xs2[RPC][Cq];  // x broadcast-packed (x,x)
    __shared__ int   s_tgt[RPC];
    __shared__ float smax[RPC][4];
    __shared__ float ssum[RPC][4];
    __shared__ float srowmax[RPC];

    int ctile = blockIdx.x;
    int r0    = blockIdx.y * RPC;
    int c0    = ctile * CPC;
    int tid   = threadIdx.x;
    int lane  = tid & 31, wid = tid >> 5;
    int c     = c0 + tid * 4;

    // load 16 rows of x, packed (x,x)
    for (int i = tid; i < RPC * Cq; i += 128) {
        int r = i / Cq, k = i - r * Cq;
        float x = g_out[(size_t)(r0 + r) * Cq + k];
        xs2[r][k] = pack2(x, x);
    }
    if (tid < RPC) s_tgt[tid] = targets[r0 + tid];
    __syncthreads();

    // bias init (padding cols get 0)
    float b0 = (c + 0 < Vq) ? lm_b[c + 0] : 0.f;
    float b1 = (c + 1 < Vq) ? lm_b[c + 1] : 0.f;
    float b2 = (c + 2 < Vq) ? lm_b[c + 2] : 0.f;
    float b3 = (c + 3 < Vq) ? lm_b[c + 3] : 0.f;
    unsigned long long acc[RPC][2];
    unsigned long long bi0 = pack2(b0, b1), bi1 = pack2(b2, b3);
    #pragma unroll
    for (int r = 0; r < RPC; r++) { acc[r][0] = bi0; acc[r][1] = bi1; }

    const float* wbase = &g_Wpad[c];
    #pragma unroll 5
    for (int k = 0; k < Cq; k++) {
        ulonglong2 w = *reinterpret_cast<const ulonglong2*>(wbase + (size_t)k * VPAD);
        #pragma unroll
        for (int r = 0; r < RPC; r++) {
            unsigned long long xv = xs2[r][k];
            fma2(acc[r][0], xv, w.x, acc[r][0]);
            fma2(acc[r][1], xv, w.y, acc[r][1]);
        }
    }

    bool v0 = (c + 0 < Vq), v1 = (c + 1 < Vq), v2 = (c + 2 < Vq), v3 = (c + 3 < Vq);

    // pass 1: store logits, capture target logit, block-reduce row max
    #pragma unroll
    for (int r = 0; r < RPC; r++) {
        float a0, a1, a2, a3;
        unpack2(acc[r][0], a0, a1);
        unpack2(acc[r][1], a2, a3);
        size_t base = (size_t)(r0 + r) * Vq + c;
        if (write_logits) {
            if (v0) logits[base + 0] = a0;
            if (v1) logits[base + 1] = a1;
            if (v2) logits[base + 2] = a2;
            if (v3) logits[base + 3] = a3;
        }
        int tg = s_tgt[r];
        if (tg >= c && tg < c + 4) {
            float tv = (tg == c) ? a0 : (tg == c + 1) ? a1 : (tg == c + 2) ? a2 : a3;
            g_tgt[r0 + r] = tv;
        }
        float m = -INFINITY;
        if (v0) m = fmaxf(m, a0);
        if (v1) m = fmaxf(m, a1);
        if (v2) m = fmaxf(m, a2);
        if (v3) m = fmaxf(m, a3);
        #pragma unroll
        for (int o = 16; o >= 1; o >>= 1) m = fmaxf(m, __shfl_xor_sync(0xffffffffu, m, o));
        if (lane == 0) smax[r][wid] = m;
    }
    __syncthreads();
    if (tid < RPC)
        srowmax[tid] = fmaxf(fmaxf(smax[tid][0], smax[tid][1]),
                             fmaxf(smax[tid][2], smax[tid][3]));
    __syncthreads();

    // pass 2: sum exp(v - rowmax)
    #pragma unroll
    for (int r = 0; r < RPC; r++) {
        float a0, a1, a2, a3;
        unpack2(acc[r][0], a0, a1);
        unpack2(acc[r][1], a2, a3);
        float M = srowmax[r];
        float s = 0.f;
        if (v0) s += __expf(a0 - M);
        if (v1) s += __expf(a1 - M);
        if (v2) s += __expf(a2 - M);
        if (v3) s += __expf(a3 - M);
        #pragma unroll
        for (int o = 16; o >= 1; o >>= 1) s += __shfl_xor_sync(0xffffffffu, s, o);
        if (lane == 0) ssum[r][wid] = s;
    }
    __syncthreads();
    if (tid < RPC) {
        float S = ssum[tid][0] + ssum[tid][1] + ssum[tid][2] + ssum[tid][3];
        g_pmax[(size_t)(r0 + tid) * NTILES + ctile] = srowmax[tid];
        g_psum[(size_t)(r0 + tid) * NTILES + ctile] = S;
    }
}

// ---------------- kernel 3: per-row logsumexp combine + partial loss ----------------
__global__ __launch_bounds__(128)
void rowloss_kernel() {
    int row = blockIdx.x * 128 + threadIdx.x;   // grid 32 x 128 = 4096
    const float* pm = &g_pmax[(size_t)row * NTILES];
    const float* ps = &g_psum[(size_t)row * NTILES];
    float M = -INFINITY;
    for (int t = 0; t < NTILES; t++) M = fmaxf(M, pm[t]);
    float S = 0.f;
    for (int t = 0; t < NTILES; t++) S += ps[t] * expf(pm[t] - M);
    float l = (M + logf(S)) - g_tgt[row];

    __shared__ float sbuf[128];
    sbuf[threadIdx.x] = l;
    __syncthreads();
    for (int o = 64; o >= 1; o >>= 1) {
        if (threadIdx.x < o) sbuf[threadIdx.x] += sbuf[threadIdx.x + o];
        __syncthreads();
    }
    if (threadIdx.x == 0) g_part[blockIdx.x] = sbuf[0];
}

// ---------------- kernel 4: final loss ----------------
__global__ void final_kernel(float* __restrict__ out, int loss_idx, int do_loss) {
    if (!do_loss) return;
    float v = g_part[threadIdx.x];   // 32 threads
    #pragma unroll
    for (int o = 16; o >= 1; o >>= 1) v += __shfl_xor_sync(0xffffffffu, v, o);
    if (threadIdx.x == 0) out[loss_idx] = v * (1.0f / (float)BT);
}

// ---------------- launch ----------------
extern "C" void kernel_launch(void* const* d_in, const int* in_sizes, int n_in,
                              void* d_out, int out_size) {
    const int*   idx     = (const int*)d_in[0];
    const int*   targets = (const int*)d_in[1];
    const float* tok_emb = (const float*)d_in[2];
    const float* pos_emb = (const float*)d_in[3];
    const float* Wq      = (const float*)d_in[4];
    const float* Wk      = (const float*)d_in[5];
    const float* Wv      = (const float*)d_in[6];
    const float* lm_W    = (const float*)d_in[7];
    const float* lm_b    = (const float*)d_in[8];
    float* out = (float*)d_out;

    const long long LOGITS = (long long)BT * Vq;   // 205,852,672
    int write_logits = (out_size >= LOGITS) ? 1 : 0;
    int do_loss = 1;
    int loss_idx;
    if (write_logits) {
        if ((long long)out_size > LOGITS) loss_idx = (int)LOGITS;   // logits + loss
        else { do_loss = 0; loss_idx = 0; }                         // logits only
    } else {
        loss_idx = out_size - 1;                                    // loss only
    }

    int n4 = Cq * VPAD / 4;
    pad_kernel<<<(n4 + 255) / 256, 256>>>(lm_W);
    attn_kernel<<<Bq, 128>>>(idx, tok_emb, pos_emb, Wq, Wk, Wv);
    logits_kernel<<<dim3(NTILES, ROWTILES), 128>>>(lm_b, targets, out, write_logits);
    rowloss_kernel<<<32, 128>>>();
    final_kernel<<<1, 32>>>(out, loss_idx, do_loss);
}

// round 3
// speedup vs baseline: 1.0537x; 1.0537x over previous
#include <cuda_runtime.h>
#include <cuda_bf16.h>
#include <cstdint>

// ---------------- problem constants ----------------
#define Bq     256
#define Tq     16
#define Cq     40
#define Hq     4
#define Dq     10
#define Vq     50257
#define BT     (Bq*Tq)          // 4096
#define VP2    50688            // padded vocab (multiple of 128, uint4-aligned rows)
#define KK     128              // split-K: [xh(40) xl(40) xh(40) 0(8)]
#define CTILE  128              // cols per CTA
#define NCT    393              // ceil(Vq/128) -- launched col tiles
#define NRT    32               // BT/128
#define NTILES 393              // partial-softmax tiles per row

// ---------------- device scratch ----------------
__device__ float           g_out[BT * Cq];
__device__ __nv_bfloat16   g_Axs[BT * KK];          // 1 MB  A[m][k]
__device__ __nv_bfloat16   g_Wt[(size_t)VP2 * KK];  // 13 MB B[n][k]
__device__ float           g_pmax[(size_t)BT * NTILES];
__device__ float           g_psum[(size_t)BT * NTILES];
__device__ float           g_tgt[BT];
__device__ float           g_part[512];

// ---------------- SMEM layout (bytes) ----------------
#define STRB   272              // padded A/B row stride in bytes (136 bf16)
#define OFF_BIAS 0              // 128 floats
#define OFF_TGT  512            // 128 ints
#define OFF_A    1024           // 128 x 272 = 34816
#define OFF_B    35840          // 128 x 272 = 34816
#define SMEM_SZ  70656
#define CSTR     132            // f32 epilogue tile stride (words); reuses OFF_A region

// ---------------- kernel: split lm_W -> g_Wt (B[n][k]) ----------------
__global__ __launch_bounds__(256)
void wprep_kernel(const float* __restrict__ lm_W) {
    int n = blockIdx.x * 256 + threadIdx.x;
    if (n >= VP2) return;
    bool valid = n < Vq;
    __nv_bfloat16 vals[KK];
    #pragma unroll
    for (int k = 0; k < 40; k++) {
        float w = valid ? lm_W[(size_t)k * Vq + n] : 0.f;
        __nv_bfloat16 h = __float2bfloat16(w);
        __nv_bfloat16 l = __float2bfloat16(w - __bfloat162float(h));
        vals[k]      = h;   // pairs with xh
        vals[40 + k] = h;   // pairs with xl
        vals[80 + k] = l;   // pairs with xh
    }
    #pragma unroll
    for (int k = 120; k < 128; k++) vals[k] = __float2bfloat16(0.f);
    const uint4* vp = reinterpret_cast<const uint4*>(vals);
    uint4* dst = reinterpret_cast<uint4*>(&g_Wt[(size_t)n * KK]);
    #pragma unroll
    for (int i = 0; i < 16; i++) dst[i] = vp[i];
}

// ---------------- kernel: embed + attention (one CTA per batch) ----------------
__global__ __launch_bounds__(128)
void attn_kernel(const int* __restrict__ idx,
                 const float* __restrict__ tok_emb,
                 const float* __restrict__ pos_emb,
                 const float* __restrict__ Wqp,
                 const float* __restrict__ Wkp,
                 const float* __restrict__ Wvp) {
    __shared__ float xs[Tq][Cq];
    __shared__ float qs[Hq][Tq][Dq];
    __shared__ float ks[Hq][Tq][Dq];
    __shared__ float vs[Hq][Tq][Dq];
    __shared__ float at[Hq][Tq][Tq];

    int b = blockIdx.x, tid = threadIdx.x;
    for (int i = tid; i < Tq * Cq; i += 128) {
        int t = i / Cq, c = i - t * Cq;
        int tok = idx[b * Tq + t];
        xs[t][c] = tok_emb[(size_t)tok * Cq + c] + pos_emb[t * Cq + c];
    }
    __syncthreads();

    int h = tid >> 5, lane = tid & 31;
    for (int i = lane; i < Tq * Dq; i += 32) {
        int t = i / Dq, d = i - t * Dq;
        float aq = 0.f, ak = 0.f, av = 0.f;
        #pragma unroll
        for (int c = 0; c < Cq; c++) {
            float x = xs[t][c];
            aq = fmaf(x, Wqp[(h * Cq + c) * Dq + d], aq);
            ak = fmaf(x, Wkp[(h * Cq + c) * Dq + d], ak);
            av = fmaf(x, Wvp[(h * Cq + c) * Dq + d], av);
        }
        qs[h][t][d] = aq; ks[h][t][d] = ak; vs[h][t][d] = av;
    }
    __syncwarp();
    for (int i = lane; i < Tq * Tq; i += 32) {
        int t = i / Tq, s = i - t * Tq;
        float a;
        if (s <= t) {
            a = 0.f;
            #pragma unroll
            for (int d = 0; d < Dq; d++) a = fmaf(qs[h][t][d], ks[h][s][d], a);
        } else a = -INFINITY;
        at[h][t][s] = a;
    }
    __syncwarp();
    if (lane < Tq) {
        int t = lane;
        float m = -INFINITY;
        for (int s = 0; s <= t; s++) m = fmaxf(m, at[h][t][s]);
        float sum = 0.f;
        for (int s = 0; s <= t; s++) { float e = expf(at[h][t][s] - m); at[h][t][s] = e; sum += e; }
        float inv = 1.f / sum;
        for (int s = 0; s <= t; s++) at[h][t][s] *= inv;
    }
    __syncwarp();
    for (int i = lane; i < Tq * Dq; i += 32) {
        int t = i / Dq, d = i - t * Dq;
        float a = 0.f;
        for (int s = 0; s <= t; s++) a = fmaf(at[h][t][s], vs[h][s][d], a);
        g_out[((size_t)(b * Tq + t)) * Cq + h * Dq + d] = a;
    }
}

// ---------------- kernel: split attention output rows -> g_Axs ----------------
__global__ __launch_bounds__(256)
void asplit_kernel() {
    int row = blockIdx.x * 256 + threadIdx.x;  // 4096 rows
    __nv_bfloat16 vals[KK];
    #pragma unroll
    for (int k = 0; k < 40; k++) {
        float x = g_out[(size_t)row * Cq + k];
        __nv_bfloat16 h = __float2bfloat16(x);
        __nv_bfloat16 l = __float2bfloat16(x - __bfloat162float(h));
        vals[k]      = h;
        vals[40 + k] = l;
        vals[80 + k] = h;
    }
    #pragma unroll
    for (int k = 120; k < 128; k++) vals[k] = __float2bfloat16(0.f);
    const uint4* vp = reinterpret_cast<const uint4*>(vals);
    uint4* dst = reinterpret_cast<uint4*>(&g_Axs[(size_t)row * KK]);
    #pragma unroll
    for (int i = 0; i < 16; i++) dst[i] = vp[i];
}

// ---------------- HMMA helper ----------------
__device__ __forceinline__ void mma16816(float* c, const uint32_t* a, const uint32_t* b) {
    asm volatile(
        "mma.sync.aligned.m16n8k16.row.col.f32.bf16.bf16.f32 "
        "{%0,%1,%2,%3}, {%4,%5,%6,%7}, {%8,%9}, {%0,%1,%2,%3};"
        : "+f"(c[0]), "+f"(c[1]), "+f"(c[2]), "+f"(c[3])
        : "r"(a[0]), "r"(a[1]), "r"(a[2]), "r"(a[3]), "r"(b[0]), "r"(b[1]));
}

// ---------------- main: HMMA GEMM 128x128 tile + fused softmax partials ----------------
__global__ __launch_bounds__(256)
void mma_kernel(const float* __restrict__ lm_b,
                const int* __restrict__ targets,
                float* __restrict__ logits,
                int write_logits) {
    extern __shared__ char smem[];
    int tid = threadIdx.x, wid = tid >> 5, lane = tid & 31;
    int ctile = blockIdx.x, rtile = blockIdx.y;
    int c0 = ctile * CTILE, r0 = rtile * 128;

    float* s_bias = reinterpret_cast<float*>(smem + OFF_BIAS);
    int*   s_tgt  = reinterpret_cast<int*>(smem + OFF_TGT);

    if (tid < 128) {
        int c = c0 + tid;
        s_bias[tid] = (c < Vq) ? lm_b[c] : 0.f;
        s_tgt[tid]  = targets[r0 + tid];
    }

    // load A tile 128 rows x 128 bf16 (padded stride 272B)
    #pragma unroll
    for (int it = 0; it < 8; it++) {
        int i = tid + it * 256;
        int m = i >> 4, k16 = i & 15;
        uint4 v = *reinterpret_cast<const uint4*>(&g_Axs[(size_t)(r0 + m) * KK + k16 * 8]);
        *reinterpret_cast<uint4*>(smem + OFF_A + m * STRB + k16 * 16) = v;
    }
    // load B tile 128 rows x 128 bf16
    #pragma unroll
    for (int it = 0; it < 8; it++) {
        int i = tid + it * 256;
        int n = i >> 4, k16 = i & 15;
        uint4 v = *reinterpret_cast<const uint4*>(&g_Wt[(size_t)(c0 + n) * KK + k16 * 8]);
        *reinterpret_cast<uint4*>(smem + OFF_B + n * STRB + k16 * 16) = v;
    }
    __syncthreads();

    // warp tiling: rows (wid&3)*32 (2 m-tiles of 16), cols (wid>>2)*64 (8 n-tiles of 8)
    int mrow0 = (wid & 3) * 32;
    int ncol0 = (wid >> 2) * 64;
    int g = lane >> 2, t = lane & 3;

    float acc[2][8][4];
    #pragma unroll
    for (int mt = 0; mt < 2; mt++)
        #pragma unroll
        for (int nt = 0; nt < 8; nt++)
            #pragma unroll
            for (int j = 0; j < 4; j++) acc[mt][nt][j] = 0.f;

    #pragma unroll
    for (int ks = 0; ks < 8; ks++) {
        uint32_t af[2][4];
        #pragma unroll
        for (int mt = 0; mt < 2; mt++) {
            const char* base = smem + OFF_A + (mrow0 + mt * 16 + g) * STRB + ks * 32 + t * 4;
            af[mt][0] = *reinterpret_cast<const uint32_t*>(base);
            af[mt][1] = *reinterpret_cast<const uint32_t*>(base + 8 * STRB);
            af[mt][2] = *reinterpret_cast<const uint32_t*>(base + 16);
            af[mt][3] = *reinterpret_cast<const uint32_t*>(base + 8 * STRB + 16);
        }
        #pragma unroll
        for (int nt = 0; nt < 8; nt++) {
            uint32_t bf[2];
            const char* bb = smem + OFF_B + (ncol0 + nt * 8 + g) * STRB + ks * 32 + t * 4;
            bf[0] = *reinterpret_cast<const uint32_t*>(bb);
            bf[1] = *reinterpret_cast<const uint32_t*>(bb + 16);
            mma16816(acc[0][nt], af[0], bf);
            mma16816(acc[1][nt], af[1], bf);
        }
    }

    __syncthreads();   // everyone done reading A/B smem before we overwrite with C

    // stage accumulators to f32 smem tile (stride 132 words), rows x cols local
    float* Cs = reinterpret_cast<float*>(smem + 1024);
    #pragma unroll
    for (int mt = 0; mt < 2; mt++) {
        #pragma unroll
        for (int nt = 0; nt < 8; nt++) {
            int row = mrow0 + mt * 16 + g;
            int col = ncol0 + nt * 8 + 2 * t;
            Cs[row * CSTR + col]           = acc[mt][nt][0];
            Cs[row * CSTR + col + 1]       = acc[mt][nt][1];
            Cs[(row + 8) * CSTR + col]     = acc[mt][nt][2];
            Cs[(row + 8) * CSTR + col + 1] = acc[mt][nt][3];
        }
    }
    __syncthreads();

    // fused epilogue: warp wid owns local rows [wid*16, wid*16+16)
    for (int i = 0; i < 16; i++) {
        int rl = wid * 16 + i;
        int grow = r0 + rl;
        int tg = s_tgt[rl];
        float4 v4 = *reinterpret_cast<const float4*>(&Cs[rl * CSTR + lane * 4]);
        float v[4];
        v[0] = v4.x + s_bias[lane * 4 + 0];
        v[1] = v4.y + s_bias[lane * 4 + 1];
        v[2] = v4.z + s_bias[lane * 4 + 2];
        v[3] = v4.w + s_bias[lane * 4 + 3];
        int cb = c0 + lane * 4;
        size_t rowbase = (size_t)grow * Vq;
        float m = -INFINITY;
        #pragma unroll
        for (int j = 0; j < 4; j++) {
            int col = cb + j;
            if (col < Vq) {
                if (write_logits) __stcs(&logits[rowbase + col], v[j]);
                if (col == tg) g_tgt[grow] = v[j];
                m = fmaxf(m, v[j]);
            }
        }
        #pragma unroll
        for (int o = 16; o >= 1; o >>= 1) m = fmaxf(m, __shfl_xor_sync(0xffffffffu, m, o));
        float s = 0.f;
        #pragma unroll
        for (int j = 0; j < 4; j++) {
            int col = cb + j;
            if (col < Vq) s += __expf(v[j] - m);
        }
        #pragma unroll
        for (int o = 16; o >= 1; o >>= 1) s += __shfl_xor_sync(0xffffffffu, s, o);
        if (lane == 0) {
            g_pmax[(size_t)grow * NTILES + ctile] = m;
            g_psum[(size_t)grow * NTILES + ctile] = s;
        }
    }
}

// ---------------- rowloss: warp per row over 393 partials ----------------
__global__ __launch_bounds__(256)
void rowloss_kernel() {
    int wid = threadIdx.x >> 5, lane = threadIdx.x & 31;
    int row = blockIdx.x * 8 + wid;   // grid 512
    const float* pm = &g_pmax[(size_t)row * NTILES];
    const float* ps = &g_psum[(size_t)row * NTILES];
    float m = -INFINITY, s = 0.f;
    for (int t = lane; t < NTILES; t += 32) {
        float tm = pm[t], ts = ps[t];
        float nm = fmaxf(m, tm);
        s = s * __expf(m - nm) + ts * __expf(tm - nm);
        m = nm;
    }
    #pragma unroll
    for (int o = 16; o >= 1; o >>= 1) {
        float om = __shfl_xor_sync(0xffffffffu, m, o);
        float os = __shfl_xor_sync(0xffffffffu, s, o);
        float nm = fmaxf(m, om);
        s = s * __expf(m - nm) + os * __expf(om - nm);
        m = nm;
    }
    __shared__ float sl[8];
    if (lane == 0) sl[wid] = (m + logf(s)) - g_tgt[row];
    __syncthreads();
    if (threadIdx.x == 0) {
        float tt = 0.f;
        #pragma unroll
        for (int w = 0; w < 8; w++) tt += sl[w];
        g_part[blockIdx.x] = tt;
    }
}

__global__ void final_kernel(float* __restrict__ out, int loss_idx, int do_loss) {
    if (!do_loss) return;
    __shared__ float sb[512];
    sb[threadIdx.x] = g_part[threadIdx.x];
    __syncthreads();
    for (int o = 256; o >= 1; o >>= 1) {
        if (threadIdx.x < o) sb[threadIdx.x] += sb[threadIdx.x + o];
        __syncthreads();
    }
    if (threadIdx.x == 0) out[loss_idx] = sb[0] * (1.0f / (float)BT);
}

// ---------------- launch ----------------
extern "C" void kernel_launch(void* const* d_in, const int* in_sizes, int n_in,
                              void* d_out, int out_size) {
    const int*   idx     = (const int*)d_in[0];
    const int*   targets = (const int*)d_in[1];
    const float* tok_emb = (const float*)d_in[2];
    const float* pos_emb = (const float*)d_in[3];
    const float* Wqp     = (const float*)d_in[4];
    const float* Wkp     = (const float*)d_in[5];
    const float* Wvp     = (const float*)d_in[6];
    const float* lm_W    = (const float*)d_in[7];
    const float* lm_b    = (const float*)d_in[8];
    float* out = (float*)d_out;

    const long long LOGITS = (long long)BT * Vq;
    int write_logits = (out_size >= LOGITS) ? 1 : 0;
    int do_loss = 1;
    int loss_idx;
    if (write_logits) {
        if ((long long)out_size > LOGITS) loss_idx = (int)LOGITS;
        else { do_loss = 0; loss_idx = 0; }
    } else {
        loss_idx = out_size - 1;
    }

    cudaFuncSetAttribute(mma_kernel, cudaFuncAttributeMaxDynamicSharedMemorySize, SMEM_SZ);

    wprep_kernel<<<(VP2 + 255) / 256, 256>>>(lm_W);
    attn_kernel<<<Bq, 128>>>(idx, tok_emb, pos_emb, Wqp, Wkp, Wvp);
    asplit_kernel<<<BT / 256, 256>>>();
    mma_kernel<<<dim3(NCT, NRT), 256, SMEM_SZ>>>(lm_b, targets, out, write_logits);
    rowloss_kernel<<<512, 256>>>();
    final_kernel<<<1, 512>>>(out, loss_idx, do_loss);
}

// round 5
// speedup vs baseline: 1.3403x; 1.2720x over previous
#include <cuda_runtime.h>
#include <cuda_bf16.h>
#include <cstdint>

// ---------------- problem constants ----------------
#define Bq     256
#define Tq     16
#define Cq     40
#define Hq     4
#define Dq     10
#define Vq     50257
#define BT     (Bq*Tq)          // 4096
#define VP2    50688            // padded vocab
#define KK     128              // split-K: [xh(40) xl(40) xh(40) 0(8)]
#define CTILE  128              // cols per CTA
#define NCT    393              // ceil(Vq/128)
#define NRT    32               // BT/128
#define NTILES 786              // partial-softmax tiles per row (64 cols each)

// ---------------- device scratch ----------------
__device__ float           g_out[BT * Cq];
__device__ __nv_bfloat16   g_Axs[BT * KK];          // A[m][k]
__device__ __nv_bfloat16   g_Wt[(size_t)VP2 * KK];  // B[n][k]
__device__ float           g_pmax[(size_t)BT * NTILES];
__device__ float           g_psum[(size_t)BT * NTILES];
__device__ float           g_tgt[BT];
__device__ float           g_part[512];

// ---------------- SMEM layout (bytes) ----------------
#define STRB     272            // padded A/B row stride in bytes (136 bf16)
#define OFF_BIAS 0              // 128 floats
#define OFF_TGT  512            // 128 ints
#define OFF_A    1024           // 128 x 272
#define OFF_B    35840          // 128 x 272
#define SMEM_SZ  70656

// ---------------- PTX helpers ----------------
__device__ __forceinline__ uint32_t smem_u32(const void* p) {
    uint32_t a;
    asm("{ .reg .u64 t; cvta.to.shared.u64 t, %1; cvt.u32.u64 %0, t; }" : "=r"(a) : "l"(p));
    return a;
}
__device__ __forceinline__ void ldm_x4(uint32_t& r0, uint32_t& r1, uint32_t& r2, uint32_t& r3,
                                       uint32_t addr) {
    asm volatile("ldmatrix.sync.aligned.m8n8.x4.shared.b16 {%0,%1,%2,%3}, [%4];"
                 : "=r"(r0), "=r"(r1), "=r"(r2), "=r"(r3) : "r"(addr));
}
__device__ __forceinline__ void mma16816(float* c, const uint32_t* a, const uint32_t* b) {
    asm volatile(
        "mma.sync.aligned.m16n8k16.row.col.f32.bf16.bf16.f32 "
        "{%0,%1,%2,%3}, {%4,%5,%6,%7}, {%8,%9}, {%0,%1,%2,%3};"
        : "+f"(c[0]), "+f"(c[1]), "+f"(c[2]), "+f"(c[3])
        : "r"(a[0]), "r"(a[1]), "r"(a[2]), "r"(a[3]), "r"(b[0]), "r"(b[1]));
}

// ---------------- kernel: split lm_W -> g_Wt (B[n][k]) ----------------
__global__ __launch_bounds__(256)
void wprep_kernel(const float* __restrict__ lm_W) {
    int n = blockIdx.x * 256 + threadIdx.x;
    if (n >= VP2) return;
    bool valid = n < Vq;
    __nv_bfloat16 vals[KK];
    #pragma unroll
    for (int k = 0; k < 40; k++) {
        float w = valid ? lm_W[(size_t)k * Vq + n] : 0.f;
        __nv_bfloat16 h = __float2bfloat16(w);
        __nv_bfloat16 l = __float2bfloat16(w - __bfloat162float(h));
        vals[k]      = h;   // pairs with xh
        vals[40 + k] = h;   // pairs with xl
        vals[80 + k] = l;   // pairs with xh
    }
    #pragma unroll
    for (int k = 120; k < 128; k++) vals[k] = __float2bfloat16(0.f);
    const uint4* vp = reinterpret_cast<const uint4*>(vals);
    uint4* dst = reinterpret_cast<uint4*>(&g_Wt[(size_t)n * KK]);
    #pragma unroll
    for (int i = 0; i < 16; i++) dst[i] = vp[i];
}

// ---------------- kernel: embed + attention (one CTA per batch) ----------------
__global__ __launch_bounds__(128)
void attn_kernel(const int* __restrict__ idx,
                 const float* __restrict__ tok_emb,
                 const float* __restrict__ pos_emb,
                 const float* __restrict__ Wqp,
                 const float* __restrict__ Wkp,
                 const float* __restrict__ Wvp) {
    __shared__ float xs[Tq][Cq];
    __shared__ float qs[Hq][Tq][Dq];
    __shared__ float ks[Hq][Tq][Dq];
    __shared__ float vs[Hq][Tq][Dq];
    __shared__ float at[Hq][Tq][Tq];

    int b = blockIdx.x, tid = threadIdx.x;
    for (int i = tid; i < Tq * Cq; i += 128) {
        int t = i / Cq, c = i - t * Cq;
        int tok = idx[b * Tq + t];
        xs[t][c] = tok_emb[(size_t)tok * Cq + c] + pos_emb[t * Cq + c];
    }
    __syncthreads();

    int h = tid >> 5, lane = tid & 31;
    for (int i = lane; i < Tq * Dq; i += 32) {
        int t = i / Dq, d = i - t * Dq;
        float aq = 0.f, ak = 0.f, av = 0.f;
        #pragma unroll
        for (int c = 0; c < Cq; c++) {
            float x = xs[t][c];
            aq = fmaf(x, Wqp[(h * Cq + c) * Dq + d], aq);
            ak = fmaf(x, Wkp[(h * Cq + c) * Dq + d], ak);
            av = fmaf(x, Wvp[(h * Cq + c) * Dq + d], av);
        }
        qs[h][t][d] = aq; ks[h][t][d] = ak; vs[h][t][d] = av;
    }
    __syncwarp();
    for (int i = lane; i < Tq * Tq; i += 32) {
        int t = i / Tq, s = i - t * Tq;
        float a;
        if (s <= t) {
            a = 0.f;
            #pragma unroll
            for (int d = 0; d < Dq; d++) a = fmaf(qs[h][t][d], ks[h][s][d], a);
        } else a = -INFINITY;
        at[h][t][s] = a;
    }
    __syncwarp();
    if (lane < Tq) {
        int t = lane;
        float m = -INFINITY;
        for (int s = 0; s <= t; s++) m = fmaxf(m, at[h][t][s]);
        float sum = 0.f;
        for (int s = 0; s <= t; s++) { float e = expf(at[h][t][s] - m); at[h][t][s] = e; sum += e; }
        float inv = 1.f / sum;
        for (int s = 0; s <= t; s++) at[h][t][s] *= inv;
    }
    __syncwarp();
    for (int i = lane; i < Tq * Dq; i += 32) {
        int t = i / Dq, d = i - t * Dq;
        float a = 0.f;
        for (int s = 0; s <= t; s++) a = fmaf(at[h][t][s], vs[h][s][d], a);
        g_out[((size_t)(b * Tq + t)) * Cq + h * Dq + d] = a;
    }
}

// ---------------- kernel: split attention output rows -> g_Axs ----------------
__global__ __launch_bounds__(256)
void asplit_kernel() {
    int row = blockIdx.x * 256 + threadIdx.x;
    __nv_bfloat16 vals[KK];
    #pragma unroll
    for (int k = 0; k < 40; k++) {
        float x = g_out[(size_t)row * Cq + k];
        __nv_bfloat16 h = __float2bfloat16(x);
        __nv_bfloat16 l = __float2bfloat16(x - __bfloat162float(h));
        vals[k]      = h;
        vals[40 + k] = l;
        vals[80 + k] = h;
    }
    #pragma unroll
    for (int k = 120; k < 128; k++) vals[k] = __float2bfloat16(0.f);
    const uint4* vp = reinterpret_cast<const uint4*>(vals);
    uint4* dst = reinterpret_cast<uint4*>(&g_Axs[(size_t)row * KK]);
    #pragma unroll
    for (int i = 0; i < 16; i++) dst[i] = vp[i];
}

// ---------------- main: HMMA GEMM 128x128 tile + fused softmax partials ----------------
__global__ __launch_bounds__(256)
void mma_kernel(const float* __restrict__ lm_b,
                const int* __restrict__ targets,
                float* __restrict__ logits,
                int write_logits) {
    extern __shared__ char smem[];
    int tid = threadIdx.x, wid = tid >> 5, lane = tid & 31;
    int ctile = blockIdx.x, rtile = blockIdx.y;
    int c0 = ctile * CTILE, r0 = rtile * 128;

    float* s_bias = reinterpret_cast<float*>(smem + OFF_BIAS);
    int*   s_tgt  = reinterpret_cast<int*>(smem + OFF_TGT);

    if (tid < 128) {
        int c = c0 + tid;
        s_bias[tid] = (c < Vq) ? lm_b[c] : 0.f;
        s_tgt[tid]  = targets[r0 + tid];
    }

    // load A tile 128 x 128 bf16 (padded stride)
    #pragma unroll
    for (int it = 0; it < 8; it++) {
        int i = tid + it * 256;
        int m = i >> 4, k16 = i & 15;
        uint4 v = *reinterpret_cast<const uint4*>(&g_Axs[(size_t)(r0 + m) * KK + k16 * 8]);
        *reinterpret_cast<uint4*>(smem + OFF_A + m * STRB + k16 * 16) = v;
    }
    // load B tile 128 x 128 bf16
    #pragma unroll
    for (int it = 0; it < 8; it++) {
        int i = tid + it * 256;
        int n = i >> 4, k16 = i & 15;
        uint4 v = *reinterpret_cast<const uint4*>(&g_Wt[(size_t)(c0 + n) * KK + k16 * 8]);
        *reinterpret_cast<uint4*>(smem + OFF_B + n * STRB + k16 * 16) = v;
    }
    __syncthreads();

    // warp tiling: rows (wid&3)*32, cols (wid>>2)*64
    int mrow0 = (wid & 3) * 32;
    int ncol0 = (wid >> 2) * 64;
    int g = lane >> 2, t = lane & 3;
    uint32_t sbase = smem_u32(smem);

    // ldmatrix per-lane source addresses
    uint32_t a_addr0 = sbase + OFF_A + (mrow0 + (lane & 15)) * STRB + (lane >> 4) * 16;
    uint32_t a_addr1 = a_addr0 + 16 * STRB;
    uint32_t b_addr0 = sbase + OFF_B + (ncol0 + ((lane >> 4) << 3) + (lane & 7)) * STRB + ((lane >> 3) & 1) * 16;
    uint32_t b_addr1 = b_addr0 + 16 * STRB;
    uint32_t b_addr2 = b_addr1 + 16 * STRB;
    uint32_t b_addr3 = b_addr2 + 16 * STRB;

    float acc[2][8][4];
    #pragma unroll
    for (int mt = 0; mt < 2; mt++)
        #pragma unroll
        for (int nt = 0; nt < 8; nt++)
            #pragma unroll
            for (int j = 0; j < 4; j++) acc[mt][nt][j] = 0.f;

    #pragma unroll
    for (int ks = 0; ks < 8; ks++) {
        uint32_t ka = ks * 32;
        uint32_t af[2][4];
        ldm_x4(af[0][0], af[0][1], af[0][2], af[0][3], a_addr0 + ka);
        ldm_x4(af[1][0], af[1][1], af[1][2], af[1][3], a_addr1 + ka);
        uint32_t bf[8][2];
        ldm_x4(bf[0][0], bf[0][1], bf[1][0], bf[1][1], b_addr0 + ka);
        ldm_x4(bf[2][0], bf[2][1], bf[3][0], bf[3][1], b_addr1 + ka);
        ldm_x4(bf[4][0], bf[4][1], bf[5][0], bf[5][1], b_addr2 + ka);
        ldm_x4(bf[6][0], bf[6][1], bf[7][0], bf[7][1], b_addr3 + ka);
        #pragma unroll
        for (int nt = 0; nt < 8; nt++) {
            mma16816(acc[0][nt], af[0], bf[nt]);
            mma16816(acc[1][nt], af[1], bf[nt]);
        }
    }

    // -------- register-direct fused epilogue (SCALAR stores: Vq odd => no vector align) ----
    int half = wid >> 2;
    int tix = ctile * 2 + half;
    bool fullcols = (c0 + CTILE) <= Vq;
    int cwb = c0 + ncol0 + 2 * t;           // this lane's first col

    float2 bs[8];
    #pragma unroll
    for (int nt = 0; nt < 8; nt++)
        bs[nt] = *reinterpret_cast<const float2*>(&s_bias[ncol0 + nt * 8 + 2 * t]);

    #pragma unroll
    for (int mt = 0; mt < 2; mt++) {
        #pragma unroll
        for (int rh = 0; rh < 2; rh++) {
            int rl = mrow0 + mt * 16 + rh * 8 + g;
            int grow = r0 + rl;
            size_t rowbase = (size_t)grow * (size_t)Vq;
            float v0[8], v1[8];
            #pragma unroll
            for (int nt = 0; nt < 8; nt++) {
                v0[nt] = acc[mt][nt][rh * 2 + 0] + bs[nt].x;
                v1[nt] = acc[mt][nt][rh * 2 + 1] + bs[nt].y;
            }
            float m = -INFINITY, s = 0.f;
            if (fullcols) {
                if (write_logits) {
                    #pragma unroll
                    for (int nt = 0; nt < 8; nt++) {
                        __stcs(&logits[rowbase + cwb + nt * 8],     v0[nt]);
                        __stcs(&logits[rowbase + cwb + nt * 8 + 1], v1[nt]);
                    }
                } else {
                    int tg = s_tgt[rl];
                    #pragma unroll
                    for (int nt = 0; nt < 8; nt++) {
                        int col = cwb + nt * 8;
                        if (col == tg) g_tgt[grow] = v0[nt];
                        if (col + 1 == tg) g_tgt[grow] = v1[nt];
                    }
                }
                #pragma unroll
                for (int nt = 0; nt < 8; nt++) m = fmaxf(m, fmaxf(v0[nt], v1[nt]));
                m = fmaxf(m, __shfl_xor_sync(0xffffffffu, m, 1));
                m = fmaxf(m, __shfl_xor_sync(0xffffffffu, m, 2));
                #pragma unroll
                for (int nt = 0; nt < 8; nt++) s += __expf(v0[nt] - m) + __expf(v1[nt] - m);
                s += __shfl_xor_sync(0xffffffffu, s, 1);
                s += __shfl_xor_sync(0xffffffffu, s, 2);
            } else {
                int tg = s_tgt[rl];
                #pragma unroll
                for (int nt = 0; nt < 8; nt++) {
                    int col = cwb + nt * 8;
                    if (col < Vq) {
                        if (write_logits) __stcs(&logits[rowbase + col], v0[nt]);
                        else if (col == tg) g_tgt[grow] = v0[nt];
                        m = fmaxf(m, v0[nt]);
                    }
                    if (col + 1 < Vq) {
                        if (write_logits) __stcs(&logits[rowbase + col + 1], v1[nt]);
                        else if (col + 1 == tg) g_tgt[grow] = v1[nt];
                        m = fmaxf(m, v1[nt]);
                    }
                }
                m = fmaxf(m, __shfl_xor_sync(0xffffffffu, m, 1));
                m = fmaxf(m, __shfl_xor_sync(0xffffffffu, m, 2));
                #pragma unroll
                for (int nt = 0; nt < 8; nt++) {
                    int col = cwb + nt * 8;
                    if (col < Vq)     s += __expf(v0[nt] - m);
                    if (col + 1 < Vq) s += __expf(v1[nt] - m);
                }
                s += __shfl_xor_sync(0xffffffffu, s, 1);
                s += __shfl_xor_sync(0xffffffffu, s, 2);
            }
            if (t == 0) {
                g_pmax[(size_t)grow * NTILES + tix] = m;
                g_psum[(size_t)grow * NTILES + tix] = s;
            }
        }
    }
}

// ---------------- target gather (after logits written) ----------------
__global__ void tgt_kernel(const int* __restrict__ targets,
                           const float* __restrict__ logits, int enable) {
    if (!enable) return;
    int row = blockIdx.x * 256 + threadIdx.x;
    g_tgt[row] = logits[(size_t)row * Vq + targets[row]];
}

// ---------------- rowloss: warp per row over 786 partials ----------------
__global__ __launch_bounds__(256)
void rowloss_kernel() {
    int wid = threadIdx.x >> 5, lane = threadIdx.x & 31;
    int row = blockIdx.x * 8 + wid;   // grid 512
    const float* pm = &g_pmax[(size_t)row * NTILES];
    const float* ps = &g_psum[(size_t)row * NTILES];
    float m = -INFINITY, s = 0.f;
    for (int t = lane; t < NTILES; t += 32) {
        float tm = pm[t], ts = ps[t];
        float nm = fmaxf(m, tm);
        s = s * __expf(m - nm) + ts * __expf(tm - nm);
        m = nm;
    }
    #pragma unroll
    for (int o = 16; o >= 1; o >>= 1) {
        float om = __shfl_xor_sync(0xffffffffu, m, o);
        float os = __shfl_xor_sync(0xffffffffu, s, o);
        float nm = fmaxf(m, om);
        s = s * __expf(m - nm) + os * __expf(om - nm);
        m = nm;
    }
    __shared__ float sl[8];
    if (lane == 0) sl[wid] = (m + logf(s)) - g_tgt[row];
    __syncthreads();
    if (threadIdx.x == 0) {
        float tt = 0.f;
        #pragma unroll
        for (int w = 0; w < 8; w++) tt += sl[w];
        g_part[blockIdx.x] = tt;
    }
}

__global__ void final_kernel(float* __restrict__ out, int loss_idx, int do_loss) {
    if (!do_loss) return;
    __shared__ float sb[512];
    sb[threadIdx.x] = g_part[threadIdx.x];
    __syncthreads();
    for (int o = 256; o >= 1; o >>= 1) {
        if (threadIdx.x < o) sb[threadIdx.x] += sb[threadIdx.x + o];
        __syncthreads();
    }
    if (threadIdx.x == 0) out[loss_idx] = sb[0] * (1.0f / (float)BT);
}

// ---------------- launch ----------------
extern "C" void kernel_launch(void* const* d_in, const int* in_sizes, int n_in,
                              void* d_out, int out_size) {
    const int*   idx     = (const int*)d_in[0];
    const int*   targets = (const int*)d_in[1];
    const float* tok_emb = (const float*)d_in[2];
    const float* pos_emb = (const float*)d_in[3];
    const float* Wqp     = (const float*)d_in[4];
    const float* Wkp     = (const float*)d_in[5];
    const float* Wvp     = (const float*)d_in[6];
    const float* lm_W    = (const float*)d_in[7];
    const float* lm_b    = (const float*)d_in[8];
    float* out = (float*)d_out;

    const long long LOGITS = (long long)BT * Vq;
    int write_logits = (out_size >= LOGITS) ? 1 : 0;
    int do_loss = 1;
    int loss_idx;
    if (write_logits) {
        if ((long long)out_size > LOGITS) loss_idx = (int)LOGITS;
        else { do_loss = 0; loss_idx = 0; }
    } else {
        loss_idx = out_size - 1;
    }

    cudaFuncSetAttribute(mma_kernel, cudaFuncAttributeMaxDynamicSharedMemorySize, SMEM_SZ);

    wprep_kernel<<<(VP2 + 255) / 256, 256>>>(lm_W);
    attn_kernel<<<Bq, 128>>>(idx, tok_emb, pos_emb, Wqp, Wkp, Wvp);
    asplit_kernel<<<BT / 256, 256>>>();
    mma_kernel<<<dim3(NCT, NRT), 256, SMEM_SZ>>>(lm_b, targets, out, write_logits);
    tgt_kernel<<<BT / 256, 256>>>(targets, out, write_logits);
    rowloss_kernel<<<512, 256>>>();
    final_kernel<<<1, 512>>>(out, loss_idx, do_loss);
}